// round 1
// baseline (speedup 1.0000x reference)
#include <cuda_runtime.h>
#include <cstdint>
#include <cstddef>

#define K_DIM 4096
#define O_DIM 11008
#define BM 128
#define BN 128
#define BK 32
#define PAD 36   // smem row stride in floats: bank = (4*row + col) % 32 -> conflict-free frag reads

__device__ __forceinline__ float to_tf32(float f) {
    unsigned u;
    asm("cvt.rna.tf32.f32 %0, %1;" : "=r"(u) : "f"(f));
    return __uint_as_float(u);
}

// C[n, o] = sum_k x[n,k] * codebook[idx[o,k]] + bias[o]
// A = x (row-major, M x K), B = dequantized weights (N=O rows, K cols), D = A @ B^T
__global__ void __launch_bounds__(256, 2)
phirho_tf32_gemm(const float* __restrict__ x,
                 const int*   __restrict__ widx,
                 const float* __restrict__ cb,
                 const float* __restrict__ bias,
                 float*       __restrict__ out)
{
    __shared__ float sA[BM][PAD];   // x tile      [m][k]
    __shared__ float sB[BN][PAD];   // weight tile [o][k] (dequantized, tf32-rounded)
    __shared__ float scb[256];      // codebook, pre-rounded to tf32

    const int tid = threadIdx.x;
    scb[tid] = to_tf32(cb[tid]);    // blockDim.x == 256 == NUM_CODES

    const int bm = blockIdx.y * BM;   // token base
    const int bn = blockIdx.x * BN;   // output-feature base

    const int warp = tid >> 5;
    const int lane = tid & 31;
    const int wm = (warp & 1) * 64;   // warp tile: 64 (M) x 32 (N)
    const int wn = (warp >> 1) * 32;
    const int g  = lane >> 2;         // groupID    (0..7)
    const int t  = lane & 3;          // tid-in-grp (0..3)

    float acc[4][4][4];
    #pragma unroll
    for (int i = 0; i < 4; i++)
        #pragma unroll
        for (int j = 0; j < 4; j++)
            #pragma unroll
            for (int c = 0; c < 4; c++)
                acc[i][j][c] = 0.0f;

    // Tile-load mapping: 256 threads -> 32 rows x 8 float4 per pass, 4 passes.
    const int lrow = tid >> 3;        // 0..31
    const int lcol = (tid & 7) * 4;   // 0,4,...,28

    const float* xg = x    + (size_t)(bm + lrow) * K_DIM + lcol;
    const int*   ig = widx + (size_t)(bn + lrow) * K_DIM + lcol;

    for (int kt = 0; kt < K_DIM; kt += BK) {
        __syncthreads();   // smem (incl. scb on iter 0) safe to (re)fill
        #pragma unroll
        for (int r = 0; r < 4; r++) {
            const int row = lrow + r * 32;
            float4 v = *(const float4*)(xg + (size_t)r * 32 * K_DIM + kt);
            sA[row][lcol + 0] = to_tf32(v.x);
            sA[row][lcol + 1] = to_tf32(v.y);
            sA[row][lcol + 2] = to_tf32(v.z);
            sA[row][lcol + 3] = to_tf32(v.w);
            int4 iv = *(const int4*)(ig + (size_t)r * 32 * K_DIM + kt);
            sB[row][lcol + 0] = scb[iv.x];
            sB[row][lcol + 1] = scb[iv.y];
            sB[row][lcol + 2] = scb[iv.z];
            sB[row][lcol + 3] = scb[iv.w];
        }
        __syncthreads();

        #pragma unroll
        for (int k8 = 0; k8 < BK; k8 += 8) {
            unsigned af[4][4], bf[4][2];
            #pragma unroll
            for (int mt = 0; mt < 4; mt++) {
                const int r = wm + mt * 16 + g;
                af[mt][0] = __float_as_uint(sA[r    ][k8 + t    ]);
                af[mt][1] = __float_as_uint(sA[r + 8][k8 + t    ]);
                af[mt][2] = __float_as_uint(sA[r    ][k8 + t + 4]);
                af[mt][3] = __float_as_uint(sA[r + 8][k8 + t + 4]);
            }
            #pragma unroll
            for (int nt = 0; nt < 4; nt++) {
                const int rn = wn + nt * 8 + g;
                bf[nt][0] = __float_as_uint(sB[rn][k8 + t    ]);
                bf[nt][1] = __float_as_uint(sB[rn][k8 + t + 4]);
            }
            #pragma unroll
            for (int mt = 0; mt < 4; mt++)
                #pragma unroll
                for (int nt = 0; nt < 4; nt++) {
                    asm volatile(
                        "mma.sync.aligned.m16n8k8.row.col.f32.tf32.tf32.f32 "
                        "{%0,%1,%2,%3}, {%4,%5,%6,%7}, {%8,%9}, {%0,%1,%2,%3};\n"
                        : "+f"(acc[mt][nt][0]), "+f"(acc[mt][nt][1]),
                          "+f"(acc[mt][nt][2]), "+f"(acc[mt][nt][3])
                        : "r"(af[mt][0]), "r"(af[mt][1]),
                          "r"(af[mt][2]), "r"(af[mt][3]),
                          "r"(bf[nt][0]), "r"(bf[nt][1]));
                }
        }
    }

    // Epilogue: add bias, store fp32. All tiles are full (8192%128==0, 11008%128==0).
    #pragma unroll
    for (int nt = 0; nt < 4; nt++) {
        const int col = bn + wn + nt * 8 + t * 2;
        const float b0 = bias[col];
        const float b1 = bias[col + 1];
        #pragma unroll
        for (int mt = 0; mt < 4; mt++) {
            const int row = bm + wm + mt * 16 + g;
            float2 v0 = make_float2(acc[mt][nt][0] + b0, acc[mt][nt][1] + b1);
            float2 v1 = make_float2(acc[mt][nt][2] + b0, acc[mt][nt][3] + b1);
            *(float2*)(out + (size_t)row       * O_DIM + col) = v0;
            *(float2*)(out + (size_t)(row + 8) * O_DIM + col) = v1;
        }
    }
}

extern "C" void kernel_launch(void* const* d_in, const int* in_sizes, int n_in,
                              void* d_out, int out_size) {
    const float* x    = (const float*)d_in[0];
    const int*   widx = (const int*)  d_in[1];
    const float* cb   = (const float*)d_in[2];
    const float* bias = (const float*)d_in[3];
    float* out = (float*)d_out;

    const int ntok = in_sizes[0] / K_DIM;       // 8192
    dim3 grid(O_DIM / BN, ntok / BM);           // (86, 64)
    phirho_tf32_gemm<<<grid, 256>>>(x, widx, cb, bias, out);
}

// round 3
// speedup vs baseline: 1.3624x; 1.3624x over previous
#include <cuda_runtime.h>
#include <cstdint>
#include <cstddef>

#define K_DIM 4096
#define O_DIM 11008
#define BM 256
#define BN 128
#define BK 32
#define THREADS 256
#define NX (O_DIM / BN)      // 86
#define KTILES (K_DIM / BK)  // 128
#define PH 8                 // panel height (M-tiles) for L2-friendly raster

#define PADF 36                      // floats per smem row (conflict-free frag reads)
#define ROWB (PADF * 4)              // 144 bytes per row (16B-aligned)
#define A_STAGE (BM * ROWB)          // 36864
#define B_STAGE (BN * ROWB)          // 18432
#define SM_CB 0
#define SM_A  1024
#define SM_B  (SM_A + 2 * A_STAGE)
#define SMEM_TOTAL (SM_B + 2 * B_STAGE)   // 111616

__device__ __forceinline__ float to_tf32(float f) {
    unsigned u;
    asm("cvt.rna.tf32.f32 %0, %1;" : "=r"(u) : "f"(f));
    return __uint_as_float(u);
}

__device__ __forceinline__ uint32_t smem_u32(const void* p) {
    uint32_t a;
    asm("{ .reg .u64 t; cvta.to.shared.u64 t, %1; cvt.u32.u64 %0, t; }" : "=r"(a) : "l"(p));
    return a;
}

__device__ __forceinline__ void cp16(uint32_t dst, const void* src) {
    asm volatile("cp.async.cg.shared.global [%0], [%1], 16;" :: "r"(dst), "l"(src));
}

__global__ void __launch_bounds__(THREADS, 1)
phirho_mma_v2(const float* __restrict__ x,
              const int*   __restrict__ widx,
              const float* __restrict__ cb,
              const float* __restrict__ bias,
              float*       __restrict__ out)
{
    extern __shared__ __align__(16) char smem[];
    const uint32_t sbase = smem_u32(smem);
    float* scb = (float*)(smem + SM_CB);

    const int tid = threadIdx.x;
    scb[tid] = to_tf32(cb[tid]);     // THREADS == 256 == NUM_CODES
    __syncthreads();                 // scb visible before any B gather

    // panel rasterization: groups of PH M-tiles sweep across all N-tiles
    const int bid = blockIdx.x;
    const int per_panel = PH * NX;
    const int panel = bid / per_panel;
    const int r0 = bid - panel * per_panel;
    const int by = panel * PH + (r0 % PH);
    const int bx = r0 / PH;
    const int bm = by * BM;
    const int bn = bx * BN;

    const int w = tid >> 5, lane = tid & 31;
    const int wm = (w >> 1) * 64;    // 4 M-blocks of 64
    const int wn = (w & 1) * 64;     // 2 N-blocks of 64
    const int g = lane >> 2;         // 0..7
    const int t = lane & 3;          // 0..3

    float acc[4][8][4];
    #pragma unroll
    for (int i = 0; i < 4; i++)
        #pragma unroll
        for (int j = 0; j < 8; j++)
            #pragma unroll
            for (int c = 0; c < 4; c++)
                acc[i][j][c] = 0.0f;

    const int frow = tid >> 3;       // 0..31 (fill row within 32-row group)
    const int fc4  = tid & 7;        // 0..7  (float4 column)

    const float* xg = x    + (size_t)(bm + frow) * K_DIM + fc4 * 4;
    const int*   ig = widx + (size_t)(bn + frow) * K_DIM + fc4 * 4;

    // ---- prologue: tile 0 into stage 0 ----
    {
        const uint32_t adst = sbase + SM_A + frow * ROWB + fc4 * 16;
        #pragma unroll
        for (int i = 0; i < 8; i++)
            cp16(adst + i * 32 * ROWB, xg + (size_t)i * 32 * K_DIM);
        asm volatile("cp.async.commit_group;" ::: "memory");

        int4 bi[4];
        #pragma unroll
        for (int i = 0; i < 4; i++)
            bi[i] = *(const int4*)(ig + (size_t)i * 32 * K_DIM);
        char* bdst = smem + SM_B + frow * ROWB + fc4 * 16;
        #pragma unroll
        for (int i = 0; i < 4; i++)
            *(float4*)(bdst + i * 32 * ROWB) =
                make_float4(scb[bi[i].x], scb[bi[i].y], scb[bi[i].z], scb[bi[i].w]);

        asm volatile("cp.async.wait_group 0;" ::: "memory");
    }
    __syncthreads();

    for (int ti = 0; ti < KTILES; ti++) {
        const int s = ti & 1, ns = s ^ 1;
        const int ktn = (ti + 1) * BK;

        int4 bi[4];
        if (ti + 1 < KTILES) {
            // prefetch next tile: A via cp.async into stage ns, idx into regs
            const uint32_t adst = sbase + SM_A + ns * A_STAGE + frow * ROWB + fc4 * 16;
            #pragma unroll
            for (int i = 0; i < 8; i++)
                cp16(adst + i * 32 * ROWB, xg + (size_t)i * 32 * K_DIM + ktn);
            asm volatile("cp.async.commit_group;" ::: "memory");
            #pragma unroll
            for (int i = 0; i < 4; i++)
                bi[i] = *(const int4*)(ig + (size_t)i * 32 * K_DIM + ktn);
        }

        // ---- compute on stage s ----
        const char* sA = smem + SM_A + s * A_STAGE;
        const char* sB = smem + SM_B + s * B_STAGE;
        #pragma unroll
        for (int k8 = 0; k8 < 4; k8++) {
            const int kb = k8 * 8;
            unsigned af[4][4], bf[8][2];
            #pragma unroll
            for (int mt = 0; mt < 4; mt++) {
                const int r = wm + mt * 16 + g;
                af[mt][0] = __float_as_uint(*(const float*)(sA + (r    ) * ROWB + (kb + t    ) * 4));
                af[mt][1] = __float_as_uint(*(const float*)(sA + (r + 8) * ROWB + (kb + t    ) * 4));
                af[mt][2] = __float_as_uint(*(const float*)(sA + (r    ) * ROWB + (kb + t + 4) * 4));
                af[mt][3] = __float_as_uint(*(const float*)(sA + (r + 8) * ROWB + (kb + t + 4) * 4));
            }
            #pragma unroll
            for (int nt = 0; nt < 8; nt++) {
                const int rn = wn + nt * 8 + g;
                bf[nt][0] = __float_as_uint(*(const float*)(sB + rn * ROWB + (kb + t    ) * 4));
                bf[nt][1] = __float_as_uint(*(const float*)(sB + rn * ROWB + (kb + t + 4) * 4));
            }
            #pragma unroll
            for (int mt = 0; mt < 4; mt++)
                #pragma unroll
                for (int nt = 0; nt < 8; nt++) {
                    asm volatile(
                        "mma.sync.aligned.m16n8k8.row.col.f32.tf32.tf32.f32 "
                        "{%0,%1,%2,%3}, {%4,%5,%6,%7}, {%8,%9}, {%0,%1,%2,%3};\n"
                        : "+f"(acc[mt][nt][0]), "+f"(acc[mt][nt][1]),
                          "+f"(acc[mt][nt][2]), "+f"(acc[mt][nt][3])
                        : "r"(af[mt][0]), "r"(af[mt][1]),
                          "r"(af[mt][2]), "r"(af[mt][3]),
                          "r"(bf[nt][0]), "r"(bf[nt][1]));
                }
        }

        if (ti + 1 < KTILES) {
            // gather-dequant B for next tile into stage ns
            char* bdst = smem + SM_B + ns * B_STAGE + frow * ROWB + fc4 * 16;
            #pragma unroll
            for (int i = 0; i < 4; i++)
                *(float4*)(bdst + i * 32 * ROWB) =
                    make_float4(scb[bi[i].x], scb[bi[i].y], scb[bi[i].z], scb[bi[i].w]);
            asm volatile("cp.async.wait_group 0;" ::: "memory");
        }
        __syncthreads();
    }

    // ---- epilogue: bias add + fp32 store (all tiles full: 8192%256==0, 11008%128==0) ----
    #pragma unroll
    for (int nt = 0; nt < 8; nt++) {
        const int col = bn + wn + nt * 8 + t * 2;
        const float b0 = bias[col];
        const float b1 = bias[col + 1];
        #pragma unroll
        for (int mt = 0; mt < 4; mt++) {
            const int row = bm + wm + mt * 16 + g;
            float2 v0 = make_float2(acc[mt][nt][0] + b0, acc[mt][nt][1] + b1);
            float2 v1 = make_float2(acc[mt][nt][2] + b0, acc[mt][nt][3] + b1);
            *(float2*)(out + (size_t)row       * O_DIM + col) = v0;
            *(float2*)(out + (size_t)(row + 8) * O_DIM + col) = v1;
        }
    }
}

extern "C" void kernel_launch(void* const* d_in, const int* in_sizes, int n_in,
                              void* d_out, int out_size) {
    const float* x    = (const float*)d_in[0];
    const int*   widx = (const int*)  d_in[1];
    const float* cb   = (const float*)d_in[2];
    const float* bias = (const float*)d_in[3];
    float* out = (float*)d_out;

    const int ntok = in_sizes[0] / K_DIM;   // 8192
    const int ny = ntok / BM;               // 32

    static bool attr_set = false;
    if (!attr_set) {
        cudaFuncSetAttribute(phirho_mma_v2,
                             cudaFuncAttributeMaxDynamicSharedMemorySize, SMEM_TOTAL);
        attr_set = true;
    }
    dim3 grid(NX * ny);                      // 2752
    phirho_mma_v2<<<grid, THREADS, SMEM_TOTAL>>>(x, widx, cb, bias, out);
}

// round 4
// speedup vs baseline: 1.4438x; 1.0597x over previous
#include <cuda_runtime.h>
#include <cstdint>
#include <cstddef>

#define K_DIM 4096
#define O_DIM 11008
#define BM 256
#define BN 128
#define BK 64
#define THREADS 256
#define NX (O_DIM / BN)      // 86
#define KT (K_DIM / BK)      // 64
#define PH 8                 // panel height (M-tiles) for L2-friendly raster

#define ROWBF 68             // floats per smem row: bank=(4*row+col)%32 -> conflict-free frags
#define ROWB  (ROWBF * 4)    // 272 bytes
#define A_STAGE (BM * ROWB)  // 69632
#define B_STAGE (BN * ROWB)  // 34816
#define STAGE   (A_STAGE + B_STAGE)     // 104448
#define SMEM_TOTAL (2 * STAGE)          // 208896

// 180MB scratch: dequantized (tf32-rounded) weights, [O_DIM][K_DIM] row-major
__device__ float g_w[(size_t)O_DIM * K_DIM];

__device__ __forceinline__ float to_tf32(float f) {
    unsigned u;
    asm("cvt.rna.tf32.f32 %0, %1;" : "=r"(u) : "f"(f));
    return __uint_as_float(u);
}

__device__ __forceinline__ uint32_t smem_u32(const void* p) {
    uint32_t a;
    asm("{ .reg .u64 t; cvta.to.shared.u64 t, %1; cvt.u32.u64 %0, t; }" : "=r"(a) : "l"(p));
    return a;
}

__device__ __forceinline__ void cp16(uint32_t dst, const void* src) {
    asm volatile("cp.async.cg.shared.global [%0], [%1], 16;" :: "r"(dst), "l"(src));
}

// ---------------- kernel 1: dequant W = tf32(cb[idx]) ----------------
__global__ void __launch_bounds__(256)
dequant_kernel(const int* __restrict__ widx, const float* __restrict__ cb)
{
    __shared__ float scb[256];
    const int tid = threadIdx.x;
    scb[tid] = to_tf32(cb[tid]);
    __syncthreads();
    const size_t i = (size_t)blockIdx.x * 256 + tid;   // float4 slot
    int4 v = ((const int4*)widx)[i];
    float4 o = make_float4(scb[v.x], scb[v.y], scb[v.z], scb[v.w]);
    ((float4*)g_w)[i] = o;
}

// ---------------- kernel 2: TF32 GEMM, A & B via cp.async ----------------
__global__ void __launch_bounds__(THREADS, 1)
phirho_gemm_v3(const float* __restrict__ x,
               const float* __restrict__ bias,
               float*       __restrict__ out)
{
    extern __shared__ __align__(16) char smem[];
    const uint32_t sbase = smem_u32(smem);
    const int tid = threadIdx.x;

    // panel rasterization
    const int bid = blockIdx.x;
    const int per_panel = PH * NX;
    const int panel = bid / per_panel;
    const int r0 = bid - panel * per_panel;
    const int by = panel * PH + (r0 % PH);
    const int bx = r0 / PH;
    const int bm = by * BM;
    const int bn = bx * BN;

    const int w = tid >> 5, lane = tid & 31;
    const int wm = (w >> 1) * 64;    // 4 M-blocks of 64
    const int wn = (w & 1) * 64;     // 2 N-blocks of 64
    const int g = lane >> 2;
    const int t = lane & 3;

    float acc[4][8][4];
    #pragma unroll
    for (int i = 0; i < 4; i++)
        #pragma unroll
        for (int j = 0; j < 8; j++)
            #pragma unroll
            for (int c = 0; c < 4; c++)
                acc[i][j][c] = 0.0f;

    // fill mapping: frow 0..15, fc4 0..15 (16B columns), rows strided by 16
    const int frow = tid >> 4;
    const int fc4  = tid & 15;

    const float* xg = x   + (size_t)(bm + frow) * K_DIM + fc4 * 4;
    const float* wg = g_w + (size_t)(bn + frow) * K_DIM + fc4 * 4;

    const uint32_t adst0 = sbase + frow * ROWB + fc4 * 16;
    const uint32_t bdst0 = sbase + A_STAGE + frow * ROWB + fc4 * 16;

    // prologue: tile 0 -> stage 0
    #pragma unroll
    for (int i = 0; i < 16; i++)
        cp16(adst0 + i * 16 * ROWB, xg + (size_t)i * 16 * K_DIM);
    #pragma unroll
    for (int j = 0; j < 8; j++)
        cp16(bdst0 + j * 16 * ROWB, wg + (size_t)j * 16 * K_DIM);
    asm volatile("cp.async.commit_group;" ::: "memory");
    asm volatile("cp.async.wait_group 0;" ::: "memory");
    __syncthreads();

    for (int ti = 0; ti < KT; ti++) {
        const int s = ti & 1, ns = s ^ 1;

        if (ti + 1 < KT) {
            const int ktn = (ti + 1) * BK;
            const uint32_t ad = adst0 + ns * STAGE;
            const uint32_t bd = bdst0 + ns * STAGE;
            #pragma unroll
            for (int i = 0; i < 16; i++)
                cp16(ad + i * 16 * ROWB, xg + (size_t)i * 16 * K_DIM + ktn);
            #pragma unroll
            for (int j = 0; j < 8; j++)
                cp16(bd + j * 16 * ROWB, wg + (size_t)j * 16 * K_DIM + ktn);
            asm volatile("cp.async.commit_group;" ::: "memory");
        }

        const char* sA = smem + s * STAGE;
        const char* sB = smem + s * STAGE + A_STAGE;

        unsigned af[2][4][4], bf[2][8][2];

        // load fragments for k8=0 into buffer 0
        #pragma unroll
        for (int mt = 0; mt < 4; mt++) {
            const int r = wm + mt * 16 + g;
            af[0][mt][0] = __float_as_uint(*(const float*)(sA + (r    ) * ROWB + (t    ) * 4));
            af[0][mt][1] = __float_as_uint(*(const float*)(sA + (r + 8) * ROWB + (t    ) * 4));
            af[0][mt][2] = __float_as_uint(*(const float*)(sA + (r    ) * ROWB + (t + 4) * 4));
            af[0][mt][3] = __float_as_uint(*(const float*)(sA + (r + 8) * ROWB + (t + 4) * 4));
        }
        #pragma unroll
        for (int nt = 0; nt < 8; nt++) {
            const int rn = wn + nt * 8 + g;
            bf[0][nt][0] = __float_as_uint(*(const float*)(sB + rn * ROWB + (t    ) * 4));
            bf[0][nt][1] = __float_as_uint(*(const float*)(sB + rn * ROWB + (t + 4) * 4));
        }

        #pragma unroll
        for (int k8 = 0; k8 < BK / 8; k8++) {
            const int cur = k8 & 1, nxt = cur ^ 1;
            if (k8 + 1 < BK / 8) {
                const int kb = (k8 + 1) * 8;
                #pragma unroll
                for (int mt = 0; mt < 4; mt++) {
                    const int r = wm + mt * 16 + g;
                    af[nxt][mt][0] = __float_as_uint(*(const float*)(sA + (r    ) * ROWB + (kb + t    ) * 4));
                    af[nxt][mt][1] = __float_as_uint(*(const float*)(sA + (r + 8) * ROWB + (kb + t    ) * 4));
                    af[nxt][mt][2] = __float_as_uint(*(const float*)(sA + (r    ) * ROWB + (kb + t + 4) * 4));
                    af[nxt][mt][3] = __float_as_uint(*(const float*)(sA + (r + 8) * ROWB + (kb + t + 4) * 4));
                }
                #pragma unroll
                for (int nt = 0; nt < 8; nt++) {
                    const int rn = wn + nt * 8 + g;
                    bf[nxt][nt][0] = __float_as_uint(*(const float*)(sB + rn * ROWB + (kb + t    ) * 4));
                    bf[nxt][nt][1] = __float_as_uint(*(const float*)(sB + rn * ROWB + (kb + t + 4) * 4));
                }
            }
            #pragma unroll
            for (int mt = 0; mt < 4; mt++)
                #pragma unroll
                for (int nt = 0; nt < 8; nt++) {
                    asm volatile(
                        "mma.sync.aligned.m16n8k8.row.col.f32.tf32.tf32.f32 "
                        "{%0,%1,%2,%3}, {%4,%5,%6,%7}, {%8,%9}, {%0,%1,%2,%3};\n"
                        : "+f"(acc[mt][nt][0]), "+f"(acc[mt][nt][1]),
                          "+f"(acc[mt][nt][2]), "+f"(acc[mt][nt][3])
                        : "r"(af[cur][mt][0]), "r"(af[cur][mt][1]),
                          "r"(af[cur][mt][2]), "r"(af[cur][mt][3]),
                          "r"(bf[cur][nt][0]), "r"(bf[cur][nt][1]));
                }
        }

        if (ti + 1 < KT)
            asm volatile("cp.async.wait_group 0;" ::: "memory");
        __syncthreads();
    }

    // epilogue: bias add + fp32 store (all tiles full)
    #pragma unroll
    for (int nt = 0; nt < 8; nt++) {
        const int col = bn + wn + nt * 8 + t * 2;
        const float b0 = bias[col];
        const float b1 = bias[col + 1];
        #pragma unroll
        for (int mt = 0; mt < 4; mt++) {
            const int row = bm + wm + mt * 16 + g;
            float2 v0 = make_float2(acc[mt][nt][0] + b0, acc[mt][nt][1] + b1);
            float2 v1 = make_float2(acc[mt][nt][2] + b0, acc[mt][nt][3] + b1);
            *(float2*)(out + (size_t)row       * O_DIM + col) = v0;
            *(float2*)(out + (size_t)(row + 8) * O_DIM + col) = v1;
        }
    }
}

extern "C" void kernel_launch(void* const* d_in, const int* in_sizes, int n_in,
                              void* d_out, int out_size) {
    const float* x    = (const float*)d_in[0];
    const int*   widx = (const int*)  d_in[1];
    const float* cb   = (const float*)d_in[2];
    const float* bias = (const float*)d_in[3];
    float* out = (float*)d_out;

    const int ntok = in_sizes[0] / K_DIM;   // 8192
    const int ny = ntok / BM;               // 32

    static bool attr_set = false;
    if (!attr_set) {
        cudaFuncSetAttribute(phirho_gemm_v3,
                             cudaFuncAttributeMaxDynamicSharedMemorySize, SMEM_TOTAL);
        attr_set = true;
    }

    // 1) dequantize weights into g_w (tf32-rounded)
    const int nvec4 = (O_DIM * K_DIM) / 4;            // 11272192
    dequant_kernel<<<nvec4 / 256, 256>>>(widx, cb);

    // 2) tensor-core GEMM
    dim3 grid(NX * ny);                               // 2752
    phirho_gemm_v3<<<grid, THREADS, SMEM_TOTAL>>>(x, bias, out);
}

// round 5
// speedup vs baseline: 1.4804x; 1.0254x over previous
#include <cuda_runtime.h>
#include <cstdint>
#include <cstddef>

#define K_DIM 4096
#define O_DIM 11008
#define BM 128
#define BN 128
#define BK 32
#define THREADS 128
#define NX (O_DIM / BN)      // 86
#define KT (K_DIM / BK)      // 128
#define PH 8                 // panel height (M-tiles) for L2-friendly raster

#define ROWBF 36             // floats per smem row: bank=(4*row+col)%32 -> conflict-free frags
#define ROWB  (ROWBF * 4)    // 144 bytes
#define A_STAGE (BM * ROWB)  // 18432
#define B_STAGE (BN * ROWB)  // 18432
#define STAGE   (A_STAGE + B_STAGE)     // 36864
#define SMEM_TOTAL (2 * STAGE)          // 73728 -> 3 CTAs/SM = 216KB

// 180MB scratch: dequantized (tf32-rounded) weights, [O_DIM][K_DIM] row-major
__device__ float g_w[(size_t)O_DIM * K_DIM];

__device__ __forceinline__ float to_tf32(float f) {
    unsigned u;
    asm("cvt.rna.tf32.f32 %0, %1;" : "=r"(u) : "f"(f));
    return __uint_as_float(u);
}

__device__ __forceinline__ uint32_t smem_u32(const void* p) {
    uint32_t a;
    asm("{ .reg .u64 t; cvta.to.shared.u64 t, %1; cvt.u32.u64 %0, t; }" : "=r"(a) : "l"(p));
    return a;
}

__device__ __forceinline__ void cp16(uint32_t dst, const void* src) {
    asm volatile("cp.async.cg.shared.global [%0], [%1], 16;" :: "r"(dst), "l"(src));
}

// ---------------- kernel 1: dequant W = tf32(cb[idx]) ----------------
__global__ void __launch_bounds__(256)
dequant_kernel(const int* __restrict__ widx, const float* __restrict__ cb)
{
    __shared__ float scb[256];
    const int tid = threadIdx.x;
    scb[tid] = to_tf32(cb[tid]);
    __syncthreads();
    const size_t i = (size_t)blockIdx.x * 256 + tid;   // float4 slot
    int4 v = ((const int4*)widx)[i];
    float4 o = make_float4(scb[v.x], scb[v.y], scb[v.z], scb[v.w]);
    ((float4*)g_w)[i] = o;
}

// ---------------- kernel 2: TF32 GEMM, 128x128 CTA, 3 CTAs/SM ----------------
__global__ void __launch_bounds__(THREADS, 3)
phirho_gemm_v4(const float* __restrict__ x,
               const float* __restrict__ bias,
               float*       __restrict__ out)
{
    extern __shared__ __align__(16) char smem[];
    const uint32_t sbase = smem_u32(smem);
    const int tid = threadIdx.x;

    // panel rasterization: PH M-tiles per panel, sweep N inside panel
    const int bid = blockIdx.x;
    const int per_panel = PH * NX;
    const int panel = bid / per_panel;
    const int r0 = bid - panel * per_panel;
    const int by = panel * PH + (r0 % PH);
    const int bx = r0 / PH;
    const int bm = by * BM;
    const int bn = bx * BN;

    const int w = tid >> 5, lane = tid & 31;
    const int wm = (w >> 1) * 64;    // 2 M-blocks of 64
    const int wn = (w & 1) * 64;     // 2 N-blocks of 64
    const int g = lane >> 2;         // 0..7
    const int t = lane & 3;          // 0..3

    float acc[4][8][4];
    #pragma unroll
    for (int i = 0; i < 4; i++)
        #pragma unroll
        for (int j = 0; j < 8; j++)
            #pragma unroll
            for (int c = 0; c < 4; c++)
                acc[i][j][c] = 0.0f;

    // fill mapping: 128 threads -> 16 rows x 8 float4 cols; 8 row-groups of 16
    const int frow = tid >> 3;       // 0..15
    const int fc4  = tid & 7;        // 0..7

    const float* xg = x   + (size_t)(bm + frow) * K_DIM + fc4 * 4;
    const float* wg = g_w + (size_t)(bn + frow) * K_DIM + fc4 * 4;

    const uint32_t adst0 = sbase + frow * ROWB + fc4 * 16;
    const uint32_t bdst0 = sbase + A_STAGE + frow * ROWB + fc4 * 16;

    // prologue: tile 0 -> stage 0
    #pragma unroll
    for (int i = 0; i < 8; i++) {
        cp16(adst0 + i * 16 * ROWB, xg + (size_t)i * 16 * K_DIM);
        cp16(bdst0 + i * 16 * ROWB, wg + (size_t)i * 16 * K_DIM);
    }
    asm volatile("cp.async.commit_group;" ::: "memory");
    asm volatile("cp.async.wait_group 0;" ::: "memory");
    __syncthreads();

    for (int ti = 0; ti < KT; ti++) {
        const int s = ti & 1, ns = s ^ 1;

        if (ti + 1 < KT) {
            const int ktn = (ti + 1) * BK;
            const uint32_t ad = adst0 + ns * STAGE;
            const uint32_t bd = bdst0 + ns * STAGE;
            #pragma unroll
            for (int i = 0; i < 8; i++) {
                cp16(ad + i * 16 * ROWB, xg + (size_t)i * 16 * K_DIM + ktn);
                cp16(bd + i * 16 * ROWB, wg + (size_t)i * 16 * K_DIM + ktn);
            }
            asm volatile("cp.async.commit_group;" ::: "memory");
        }

        const char* sA = smem + s * STAGE;
        const char* sB = smem + s * STAGE + A_STAGE;

        #pragma unroll
        for (int k8 = 0; k8 < BK / 8; k8++) {
            const int kb = k8 * 8;
            unsigned af[4][4], bf[8][2];
            #pragma unroll
            for (int mt = 0; mt < 4; mt++) {
                const int r = wm + mt * 16 + g;
                af[mt][0] = __float_as_uint(*(const float*)(sA + (r    ) * ROWB + (kb + t    ) * 4));
                af[mt][1] = __float_as_uint(*(const float*)(sA + (r + 8) * ROWB + (kb + t    ) * 4));
                af[mt][2] = __float_as_uint(*(const float*)(sA + (r    ) * ROWB + (kb + t + 4) * 4));
                af[mt][3] = __float_as_uint(*(const float*)(sA + (r + 8) * ROWB + (kb + t + 4) * 4));
            }
            #pragma unroll
            for (int nt = 0; nt < 8; nt++) {
                const int rn = wn + nt * 8 + g;
                bf[nt][0] = __float_as_uint(*(const float*)(sB + rn * ROWB + (kb + t    ) * 4));
                bf[nt][1] = __float_as_uint(*(const float*)(sB + rn * ROWB + (kb + t + 4) * 4));
            }
            #pragma unroll
            for (int mt = 0; mt < 4; mt++)
                #pragma unroll
                for (int nt = 0; nt < 8; nt++) {
                    asm volatile(
                        "mma.sync.aligned.m16n8k8.row.col.f32.tf32.tf32.f32 "
                        "{%0,%1,%2,%3}, {%4,%5,%6,%7}, {%8,%9}, {%0,%1,%2,%3};\n"
                        : "+f"(acc[mt][nt][0]), "+f"(acc[mt][nt][1]),
                          "+f"(acc[mt][nt][2]), "+f"(acc[mt][nt][3])
                        : "r"(af[mt][0]), "r"(af[mt][1]),
                          "r"(af[mt][2]), "r"(af[mt][3]),
                          "r"(bf[nt][0]), "r"(bf[nt][1]));
                }
        }

        if (ti + 1 < KT)
            asm volatile("cp.async.wait_group 0;" ::: "memory");
        __syncthreads();
    }

    // epilogue: bias add + fp32 store (all tiles full: 8192%128==0, 11008%128==0)
    #pragma unroll
    for (int nt = 0; nt < 8; nt++) {
        const int col = bn + wn + nt * 8 + t * 2;
        const float b0 = bias[col];
        const float b1 = bias[col + 1];
        #pragma unroll
        for (int mt = 0; mt < 4; mt++) {
            const int row = bm + wm + mt * 16 + g;
            float2 v0 = make_float2(acc[mt][nt][0] + b0, acc[mt][nt][1] + b1);
            float2 v1 = make_float2(acc[mt][nt][2] + b0, acc[mt][nt][3] + b1);
            *(float2*)(out + (size_t)row       * O_DIM + col) = v0;
            *(float2*)(out + (size_t)(row + 8) * O_DIM + col) = v1;
        }
    }
}

extern "C" void kernel_launch(void* const* d_in, const int* in_sizes, int n_in,
                              void* d_out, int out_size) {
    const float* x    = (const float*)d_in[0];
    const int*   widx = (const int*)  d_in[1];
    const float* cb   = (const float*)d_in[2];
    const float* bias = (const float*)d_in[3];
    float* out = (float*)d_out;

    const int ntok = in_sizes[0] / K_DIM;   // 8192
    const int ny = ntok / BM;               // 64

    static bool attr_set = false;
    if (!attr_set) {
        cudaFuncSetAttribute(phirho_gemm_v4,
                             cudaFuncAttributeMaxDynamicSharedMemorySize, SMEM_TOTAL);
        attr_set = true;
    }

    // 1) dequantize weights into g_w (tf32-rounded)
    const int nvec4 = (O_DIM * K_DIM) / 4;            // 11272192
    dequant_kernel<<<nvec4 / 256, 256>>>(widx, cb);

    // 2) tensor-core GEMM
    dim3 grid(NX * ny);                               // 5504
    phirho_gemm_v4<<<grid, THREADS, SMEM_TOTAL>>>(x, bias, out);
}